// round 2
// baseline (speedup 1.0000x reference)
#include <cuda_runtime.h>

// Problem constants
#define BQ    8192
#define NSUB  16
#define KC    1024
#define EDIM  16
#define DEPTHQ 3
#define DIMQ  256

// Output layout (flattened concat of reference outputs, float32):
// [loss(1), z_q_out(B*256), onehot(B*16*1024), idx(B*16)]
#define OFF_LOSS   ((size_t)0)
#define OFF_ZQ     ((size_t)1)
#define OFF_ONEHOT ((size_t)(1 + BQ * DIMQ))
#define OFF_IDX    ((size_t)(OFF_ONEHOT + (size_t)BQ * NSUB * KC))

// Scratch (static device globals: allowed)
__device__ float g_P[(size_t)NSUB * KC * DIMQ];     // P[n][k][j] = emb[n][k][:] @ W[16n:16n+16][:,j]
__device__ int   g_idx[(size_t)BQ * NSUB * DEPTHQ]; // idx per (b,n,depth)

// ---------------- packed f32x2 helpers ----------------
__device__ __forceinline__ unsigned long long pack2(float a, float b) {
    unsigned long long r;
    asm("mov.b64 %0, {%1,%2};" : "=l"(r) : "f"(a), "f"(b));
    return r;
}
__device__ __forceinline__ void fma2(unsigned long long& d, unsigned long long a, unsigned long long b) {
    asm("fma.rn.f32x2 %0, %1, %2, %0;" : "+l"(d) : "l"(a), "l"(b));
}
__device__ __forceinline__ void unpack2(unsigned long long v, float& lo, float& hi) {
    asm("mov.b64 {%0,%1}, %2;" : "=f"(lo), "=f"(hi) : "l"(v));
}

// ---------------- kernel 1: P precompute (+ zero loss slot) ----------------
__global__ void compute_P_kernel(const float* __restrict__ emb,
                                 const float* __restrict__ W,
                                 float* __restrict__ out) {
    if (blockIdx.x == 0 && threadIdx.x == 0) out[OFF_LOSS] = 0.0f;

    const int n  = blockIdx.x >> 2;
    const int k0 = (blockIdx.x & 3) * 256;
    const int j  = threadIdx.x;

    float w[16];
#pragma unroll
    for (int i = 0; i < 16; i++) w[i] = W[(size_t)(n * 16 + i) * DIMQ + j];

    for (int kk = 0; kk < 256; kk++) {
        const int k = k0 + kk;
        const float* e = emb + ((size_t)n * KC + k) * EDIM;
        float acc = 0.0f;
#pragma unroll
        for (int i = 0; i < 16; i++) acc = fmaf(__ldg(e + i), w[i], acc);
        g_P[((size_t)n * KC + k) * DIMQ + j] = acc;
    }
}

// ---------------- kernel 2: VQ search (3 depths), reference-mimicking numerics ----------------
// grid (8 row-tiles of 1024 rows, 16 n), 256 threads.
// Rows per thread: b(r) = rowbase + r*256 + tid, r=0..3, packed as lane pairs (r0,r1),(r2,r3).
// SMEM: duplicated codebook mc[k][16] as u64 (e_i in both lanes) 128KB + esq[1024] 4KB + s_last[1024] 4KB.
#define VQ_SMEM ((size_t)(KC * 16 * 8 + KC * 4 + 1024 * 4))

__global__ void __launch_bounds__(256, 1)
vq_kernel(const float* __restrict__ z,
          const float* __restrict__ emb,
          float* __restrict__ out) {
    extern __shared__ unsigned long long sm[];
    unsigned long long* mc = sm;                        // mc[k*16 + i] = (e_i, e_i)
    float* s_esq = (float*)(sm + (size_t)KC * 16);      // esq[k]
    int*   s_last = (int*)(s_esq + KC);                 // last-depth idx per local row

    const float* mcf = (const float*)mc;                // float view: e_i at [k*32 + 2*i]

    const int n = blockIdx.y;
    const int rowbase = blockIdx.x * 1024;
    const int tid = threadIdx.x;

    // Build duplicated codebook + e_sq (sequential fmaf chain, matching jnp.sum(e*e,-1))
    for (int k = tid; k < KC; k += 256) {
        const float* e = emb + ((size_t)n * KC + k) * EDIM;
        float esqv = 0.0f;
        unsigned long long* m = mc + (size_t)k * 16;
#pragma unroll
        for (int i = 0; i < 16; i++) {
            float v = __ldg(e + i);
            esqv = fmaf(v, v, esqv);
            m[i] = pack2(v, v);
        }
        s_esq[k] = esqv;
    }
    __syncthreads();

    // Load residuals: pair p packs rows b(2p) (lo lane) and b(2p+1) (hi lane)
    unsigned long long zp[2][16];
    float zsq[4];
#pragma unroll
    for (int p = 0; p < 2; p++) {
        const int bA = rowbase + (2 * p) * 256 + tid;
        const int bB = rowbase + (2 * p + 1) * 256 + tid;
        const float* zA = z + (size_t)bA * DIMQ + n * EDIM;
        const float* zB = z + (size_t)bB * DIMQ + n * EDIM;
        float sA = 0.0f, sB = 0.0f;
#pragma unroll
        for (int i = 0; i < 16; i++) {
            float a = zA[i], b = zB[i];
            zp[p][i] = pack2(a, b);
            sA = fmaf(a, a, sA);
            sB = fmaf(b, b, sB);
        }
        zsq[2 * p] = sA;
        zsq[2 * p + 1] = sB;
    }

    for (int d = 0; d < DEPTHQ; d++) {
        float bs[4], bd[4];
        int bk[4];
#pragma unroll
        for (int r = 0; r < 4; r++) { bs[r] = 3.4e38f; bd[r] = 3.4e38f; bk[r] = 0; }

        for (int k = 0; k < KC; ++k) {
            const ulonglong2* mv = (const ulonglong2*)(mc + (size_t)k * 16);
            ulonglong2 m0 = mv[0], m1 = mv[1], m2 = mv[2], m3 = mv[3];
            ulonglong2 m4 = mv[4], m5 = mv[5], m6 = mv[6], m7 = mv[7];

            unsigned long long acc0 = 0ull, acc1 = 0ull;
            // sequential i = 0..15 per lane (bit-matches scalar fmaf chain)
            fma2(acc0, zp[0][0],  m0.x); fma2(acc1, zp[1][0],  m0.x);
            fma2(acc0, zp[0][1],  m0.y); fma2(acc1, zp[1][1],  m0.y);
            fma2(acc0, zp[0][2],  m1.x); fma2(acc1, zp[1][2],  m1.x);
            fma2(acc0, zp[0][3],  m1.y); fma2(acc1, zp[1][3],  m1.y);
            fma2(acc0, zp[0][4],  m2.x); fma2(acc1, zp[1][4],  m2.x);
            fma2(acc0, zp[0][5],  m2.y); fma2(acc1, zp[1][5],  m2.y);
            fma2(acc0, zp[0][6],  m3.x); fma2(acc1, zp[1][6],  m3.x);
            fma2(acc0, zp[0][7],  m3.y); fma2(acc1, zp[1][7],  m3.y);
            fma2(acc0, zp[0][8],  m4.x); fma2(acc1, zp[1][8],  m4.x);
            fma2(acc0, zp[0][9],  m4.y); fma2(acc1, zp[1][9],  m4.y);
            fma2(acc0, zp[0][10], m5.x); fma2(acc1, zp[1][10], m5.x);
            fma2(acc0, zp[0][11], m5.y); fma2(acc1, zp[1][11], m5.y);
            fma2(acc0, zp[0][12], m6.x); fma2(acc1, zp[1][12], m6.x);
            fma2(acc0, zp[0][13], m6.y); fma2(acc1, zp[1][13], m6.y);
            fma2(acc0, zp[0][14], m7.x); fma2(acc1, zp[1][14], m7.x);
            fma2(acc0, zp[0][15], m7.y); fma2(acc1, zp[1][15], m7.y);

            const float es = s_esq[k];
            float c[4];
            unpack2(acc0, c[0], c[1]);
            unpack2(acc1, c[2], c[3]);
#pragma unroll
            for (int r = 0; r < 4; r++) {
                // fmaf(-2,c,zsq) bit-equals (zsq - 2.0f*c) since 2*c is exact
                float s = fmaf(-2.0f, c[r], zsq[r]) + es;
                if (s < bs[r]) {
                    // reference compares d = sqrt(max(s,0)); sqrt can collapse
                    // adjacent s values -> equal d -> argmin keeps lower index
                    float dv = sqrtf(fmaxf(s, 0.0f));
                    if (dv < bd[r]) { bd[r] = dv; bk[r] = k; }
                    bs[r] = s;
                }
            }
        }

        // Residual update zr -= e[bk] (one fp32 sub per component, matching ref),
        // recompute zsq via sequential fmaf chain; record indices.
#pragma unroll
        for (int p = 0; p < 2; p++) {
            const int kA = bk[2 * p], kB = bk[2 * p + 1];
            float sA = 0.0f, sB = 0.0f;
#pragma unroll
            for (int i = 0; i < 16; i++) {
                float a, b;
                unpack2(zp[p][i], a, b);
                a = a - mcf[(size_t)kA * 32 + 2 * i];
                b = b - mcf[(size_t)kB * 32 + 2 * i];
                sA = fmaf(a, a, sA);
                sB = fmaf(b, b, sB);
                zp[p][i] = pack2(a, b);
            }
            zsq[2 * p] = sA;
            zsq[2 * p + 1] = sB;
        }
#pragma unroll
        for (int r = 0; r < 4; r++) {
            const int b = rowbase + r * 256 + tid;
            g_idx[((size_t)b * NSUB + n) * DEPTHQ + d] = bk[r];
            if (d == DEPTHQ - 1) {
                s_last[r * 256 + tid] = bk[r];
                out[OFF_IDX + (size_t)b * NSUB + n] = (float)bk[r];
            }
        }
    }
    __syncthreads();

    // Onehot rows (last depth): coalesced per-row warp writes
    const int w = tid >> 5, lane = tid & 31;
    for (int rl = w * 128; rl < (w + 1) * 128; rl++) {
        const int b = rowbase + rl;
        const int k1 = s_last[rl];
        float* dst = out + OFF_ONEHOT + ((size_t)b * NSUB + n) * KC;
        for (int j = lane; j < KC; j += 32) dst[j] = (j == k1) ? 1.0f : 0.0f;
    }
}

// ---------------- kernel 3: z_q gather + z_q_out + loss ----------------
__global__ void gather_out_kernel(const float* __restrict__ z,
                                  const float* __restrict__ bias,
                                  float* __restrict__ out) {
    const int b = blockIdx.x;
    const int j = threadIdx.x;
    __shared__ int sidx[48];
    __shared__ float sred[8];

    if (j < 48) sidx[j] = g_idx[(size_t)b * 48 + j];
    __syncthreads();

    float acc = 0.0f;
#pragma unroll
    for (int n = 0; n < NSUB; n++) {
#pragma unroll
        for (int d = 0; d < DEPTHQ; d++) {
            const int k = sidx[n * 3 + d];
            acc += g_P[(((size_t)n << 10) + k) * DIMQ + j];
        }
    }
    const float zq = acc * (1.0f / 3.0f) + bias[j];
    const float zv = z[(size_t)b * DIMQ + j];
    const float diff = zq - zv;
    out[OFF_ZQ + (size_t)b * DIMQ + j] = zv + diff;

    float p = diff * diff;
#pragma unroll
    for (int off = 16; off > 0; off >>= 1) p += __shfl_down_sync(0xffffffffu, p, off);
    if ((j & 31) == 0) sred[j >> 5] = p;
    __syncthreads();
    if (j == 0) {
        float s = 0.0f;
#pragma unroll
        for (int i = 0; i < 8; i++) s += sred[i];
        atomicAdd(out + OFF_LOSS, s * (1.25f / (float)(BQ * DIMQ)));
    }
}

// ---------------- launcher ----------------
extern "C" void kernel_launch(void* const* d_in, const int* in_sizes, int n_in,
                              void* d_out, int out_size) {
    const float* z    = (const float*)d_in[0];
    const float* emb  = (const float*)d_in[1];
    const float* W    = (const float*)d_in[2];
    const float* bias = (const float*)d_in[3];
    float* out = (float*)d_out;

    (void)in_sizes; (void)n_in; (void)out_size;

    compute_P_kernel<<<64, 256>>>(emb, W, out);

    cudaFuncSetAttribute(vq_kernel, cudaFuncAttributeMaxDynamicSharedMemorySize, (int)VQ_SMEM);
    vq_kernel<<<dim3(8, 16), 256, VQ_SMEM>>>(z, emb, out);

    gather_out_kernel<<<BQ, 256>>>(z, bias, out);
}

// round 3
// speedup vs baseline: 1.3424x; 1.3424x over previous
#include <cuda_runtime.h>

// Problem constants
#define BQ    8192
#define NSUB  16
#define KC    1024
#define EDIM  16
#define DEPTHQ 3
#define DIMQ  256

// Output layout (flattened concat of reference outputs, float32):
// [loss(1), z_q_out(B*256), onehot(B*16*1024), idx(B*16)]
#define OFF_LOSS   ((size_t)0)
#define OFF_ZQ     ((size_t)1)
#define OFF_ONEHOT ((size_t)(1 + BQ * DIMQ))
#define OFF_IDX    ((size_t)(OFF_ONEHOT + (size_t)BQ * NSUB * KC))

// Scratch (static device globals: allowed)
__device__ float g_P[(size_t)NSUB * KC * DIMQ];     // P[n][k][j] = emb[n][k][:] @ W[16n:16n+16][:,j]
__device__ int   g_idx[(size_t)BQ * NSUB * DEPTHQ]; // idx per (b,n,depth)

// ---------------- packed f32x2 helpers ----------------
__device__ __forceinline__ unsigned long long pack2(float a, float b) {
    unsigned long long r;
    asm("mov.b64 %0, {%1,%2};" : "=l"(r) : "f"(a), "f"(b));
    return r;
}
__device__ __forceinline__ void fma2(unsigned long long& d, unsigned long long a, unsigned long long b) {
    asm("fma.rn.f32x2 %0, %1, %2, %0;" : "+l"(d) : "l"(a), "l"(b));
}
__device__ __forceinline__ void unpack2(unsigned long long v, float& lo, float& hi) {
    asm("mov.b64 {%0,%1}, %2;" : "=f"(lo), "=f"(hi) : "l"(v));
}

// ---------------- kernel 1: P precompute (+ zero loss slot) ----------------
// grid 1024 = (n=16) x (kchunk=64, 16 k each), 256 threads (j = output col)
__global__ void compute_P_kernel(const float* __restrict__ emb,
                                 const float* __restrict__ W,
                                 float* __restrict__ out) {
    if (blockIdx.x == 0 && threadIdx.x == 0) out[OFF_LOSS] = 0.0f;

    const int n  = blockIdx.x >> 6;
    const int k0 = (blockIdx.x & 63) * 16;
    const int j  = threadIdx.x;

    __shared__ float se[16 * EDIM];  // e[k0..k0+15][0..15]
    se[j] = emb[((size_t)n * KC + k0) * EDIM + j];

    float w[16];
#pragma unroll
    for (int i = 0; i < 16; i++) w[i] = W[(size_t)(n * 16 + i) * DIMQ + j];
    __syncthreads();

#pragma unroll
    for (int kk = 0; kk < 16; kk++) {
        float acc = 0.0f;
#pragma unroll
        for (int i = 0; i < 16; i++) acc = fmaf(se[kk * EDIM + i], w[i], acc);
        g_P[((size_t)n * KC + (k0 + kk)) * DIMQ + j] = acc;
    }
}

// ---------------- kernel 2: VQ search (3 depths), reference-mimicking numerics ----------------
// grid (8 row-tiles of 1024 rows, 16 n), 256 threads.
// Rows per thread: b(r) = rowbase + r*256 + tid, r=0..3, packed as lane pairs (r0,r1),(r2,r3).
// SMEM: duplicated codebook mc[k][16] as u64 (e_i in both lanes) 128KB + esq[1024] 4KB + s_last[1024] 4KB.
#define VQ_SMEM ((size_t)(KC * 16 * 8 + KC * 4 + 1024 * 4))

__global__ void __launch_bounds__(256, 1)
vq_kernel(const float* __restrict__ z,
          const float* __restrict__ emb,
          float* __restrict__ out) {
    extern __shared__ unsigned long long sm[];
    unsigned long long* mc = sm;                        // mc[k*16 + i] = (e_i, e_i)
    float* s_esq = (float*)(sm + (size_t)KC * 16);      // esq[k]
    int*   s_last = (int*)(s_esq + KC);                 // last-depth idx per local row

    const float* mcf = (const float*)mc;                // float view: e_i at [k*32 + 2*i]

    const int n = blockIdx.y;
    const int rowbase = blockIdx.x * 1024;
    const int tid = threadIdx.x;

    // Build duplicated codebook + e_sq (sequential fmaf chain, matching jnp.sum(e*e,-1))
    for (int k = tid; k < KC; k += 256) {
        const float* e = emb + ((size_t)n * KC + k) * EDIM;
        float esqv = 0.0f;
        unsigned long long* m = mc + (size_t)k * 16;
#pragma unroll
        for (int i = 0; i < 16; i++) {
            float v = __ldg(e + i);
            esqv = fmaf(v, v, esqv);
            m[i] = pack2(v, v);
        }
        s_esq[k] = esqv;
    }
    __syncthreads();

    // Load residuals: pair p packs rows b(2p) (lo lane) and b(2p+1) (hi lane)
    unsigned long long zp[2][16];
    float zsq[4];
#pragma unroll
    for (int p = 0; p < 2; p++) {
        const int bA = rowbase + (2 * p) * 256 + tid;
        const int bB = rowbase + (2 * p + 1) * 256 + tid;
        const float* zA = z + (size_t)bA * DIMQ + n * EDIM;
        const float* zB = z + (size_t)bB * DIMQ + n * EDIM;
        float sA = 0.0f, sB = 0.0f;
#pragma unroll
        for (int i = 0; i < 16; i++) {
            float a = zA[i], b = zB[i];
            zp[p][i] = pack2(a, b);
            sA = fmaf(a, a, sA);
            sB = fmaf(b, b, sB);
        }
        zsq[2 * p] = sA;
        zsq[2 * p + 1] = sB;
    }

    for (int d = 0; d < DEPTHQ; d++) {
        float bs[4], bd[4];
        int bk[4];
#pragma unroll
        for (int r = 0; r < 4; r++) { bs[r] = 3.4e38f; bd[r] = 3.4e38f; bk[r] = 0; }

#pragma unroll 2
        for (int k = 0; k < KC; ++k) {
            const ulonglong2* mv = (const ulonglong2*)(mc + (size_t)k * 16);
            ulonglong2 m0 = mv[0], m1 = mv[1], m2 = mv[2], m3 = mv[3];
            ulonglong2 m4 = mv[4], m5 = mv[5], m6 = mv[6], m7 = mv[7];

            unsigned long long acc0 = 0ull, acc1 = 0ull;
            // sequential i = 0..15 per lane (bit-matches scalar fmaf chain)
            fma2(acc0, zp[0][0],  m0.x); fma2(acc1, zp[1][0],  m0.x);
            fma2(acc0, zp[0][1],  m0.y); fma2(acc1, zp[1][1],  m0.y);
            fma2(acc0, zp[0][2],  m1.x); fma2(acc1, zp[1][2],  m1.x);
            fma2(acc0, zp[0][3],  m1.y); fma2(acc1, zp[1][3],  m1.y);
            fma2(acc0, zp[0][4],  m2.x); fma2(acc1, zp[1][4],  m2.x);
            fma2(acc0, zp[0][5],  m2.y); fma2(acc1, zp[1][5],  m2.y);
            fma2(acc0, zp[0][6],  m3.x); fma2(acc1, zp[1][6],  m3.x);
            fma2(acc0, zp[0][7],  m3.y); fma2(acc1, zp[1][7],  m3.y);
            fma2(acc0, zp[0][8],  m4.x); fma2(acc1, zp[1][8],  m4.x);
            fma2(acc0, zp[0][9],  m4.y); fma2(acc1, zp[1][9],  m4.y);
            fma2(acc0, zp[0][10], m5.x); fma2(acc1, zp[1][10], m5.x);
            fma2(acc0, zp[0][11], m5.y); fma2(acc1, zp[1][11], m5.y);
            fma2(acc0, zp[0][12], m6.x); fma2(acc1, zp[1][12], m6.x);
            fma2(acc0, zp[0][13], m6.y); fma2(acc1, zp[1][13], m6.y);
            fma2(acc0, zp[0][14], m7.x); fma2(acc1, zp[1][14], m7.x);
            fma2(acc0, zp[0][15], m7.y); fma2(acc1, zp[1][15], m7.y);

            const float es = s_esq[k];
            float c[4];
            unpack2(acc0, c[0], c[1]);
            unpack2(acc1, c[2], c[3]);

            // fmaf(-2,c,zsq) bit-equals (zsq - 2.0f*c) since 2*c is exact
            float s0 = fmaf(-2.0f, c[0], zsq[0]) + es;
            float s1 = fmaf(-2.0f, c[1], zsq[1]) + es;
            float s2 = fmaf(-2.0f, c[2], zsq[2]) + es;
            float s3 = fmaf(-2.0f, c[3], zsq[3]) + es;

            const bool c0 = s0 < bs[0];
            const bool c1 = s1 < bs[1];
            const bool c2 = s2 < bs[2];
            const bool c3 = s3 < bs[3];
            bs[0] = fminf(bs[0], s0);
            bs[1] = fminf(bs[1], s1);
            bs[2] = fminf(bs[2], s2);
            bs[3] = fminf(bs[3], s3);

            // One grouped rare-path region instead of 4 per-row branch regions.
            // reference compares d = sqrt(max(s,0)); sqrt can collapse adjacent
            // s values -> equal d -> argmin keeps lower index. Only a strictly
            // smaller s can possibly produce a smaller d, so the sqrt is rare.
            if (c0 | c1 | c2 | c3) {
                if (c0) { float dv = sqrtf(fmaxf(s0, 0.0f)); if (dv < bd[0]) { bd[0] = dv; bk[0] = k; } }
                if (c1) { float dv = sqrtf(fmaxf(s1, 0.0f)); if (dv < bd[1]) { bd[1] = dv; bk[1] = k; } }
                if (c2) { float dv = sqrtf(fmaxf(s2, 0.0f)); if (dv < bd[2]) { bd[2] = dv; bk[2] = k; } }
                if (c3) { float dv = sqrtf(fmaxf(s3, 0.0f)); if (dv < bd[3]) { bd[3] = dv; bk[3] = k; } }
            }
        }

        // Residual update zr -= e[bk] (one fp32 sub per component, matching ref),
        // recompute zsq via sequential fmaf chain; record indices.
#pragma unroll
        for (int p = 0; p < 2; p++) {
            const int kA = bk[2 * p], kB = bk[2 * p + 1];
            float sA = 0.0f, sB = 0.0f;
#pragma unroll
            for (int i = 0; i < 16; i++) {
                float a, b;
                unpack2(zp[p][i], a, b);
                a = a - mcf[(size_t)kA * 32 + 2 * i];
                b = b - mcf[(size_t)kB * 32 + 2 * i];
                sA = fmaf(a, a, sA);
                sB = fmaf(b, b, sB);
                zp[p][i] = pack2(a, b);
            }
            zsq[2 * p] = sA;
            zsq[2 * p + 1] = sB;
        }
#pragma unroll
        for (int r = 0; r < 4; r++) {
            const int b = rowbase + r * 256 + tid;
            g_idx[((size_t)b * NSUB + n) * DEPTHQ + d] = bk[r];
            if (d == DEPTHQ - 1) {
                s_last[r * 256 + tid] = bk[r];
                out[OFF_IDX + (size_t)b * NSUB + n] = (float)bk[r];
            }
        }
    }
    __syncthreads();

    // Onehot rows (last depth): coalesced per-row warp writes
    const int w = tid >> 5, lane = tid & 31;
    for (int rl = w * 128; rl < (w + 1) * 128; rl++) {
        const int b = rowbase + rl;
        const int k1 = s_last[rl];
        float* dst = out + OFF_ONEHOT + ((size_t)b * NSUB + n) * KC;
        for (int j = lane; j < KC; j += 32) dst[j] = (j == k1) ? 1.0f : 0.0f;
    }
}

// ---------------- kernel 3: z_q gather + z_q_out + loss ----------------
__global__ void gather_out_kernel(const float* __restrict__ z,
                                  const float* __restrict__ bias,
                                  float* __restrict__ out) {
    const int b = blockIdx.x;
    const int j = threadIdx.x;
    __shared__ int sidx[48];
    __shared__ float sred[8];

    if (j < 48) sidx[j] = g_idx[(size_t)b * 48 + j];
    __syncthreads();

    float acc = 0.0f;
#pragma unroll
    for (int n = 0; n < NSUB; n++) {
#pragma unroll
        for (int d = 0; d < DEPTHQ; d++) {
            const int k = sidx[n * 3 + d];
            acc += g_P[(((size_t)n << 10) + k) * DIMQ + j];
        }
    }
    const float zq = acc * (1.0f / 3.0f) + bias[j];
    const float zv = z[(size_t)b * DIMQ + j];
    const float diff = zq - zv;
    out[OFF_ZQ + (size_t)b * DIMQ + j] = zv + diff;

    float p = diff * diff;
#pragma unroll
    for (int off = 16; off > 0; off >>= 1) p += __shfl_down_sync(0xffffffffu, p, off);
    if ((j & 31) == 0) sred[j >> 5] = p;
    __syncthreads();
    if (j == 0) {
        float s = 0.0f;
#pragma unroll
        for (int i = 0; i < 8; i++) s += sred[i];
        atomicAdd(out + OFF_LOSS, s * (1.25f / (float)(BQ * DIMQ)));
    }
}

// ---------------- launcher ----------------
extern "C" void kernel_launch(void* const* d_in, const int* in_sizes, int n_in,
                              void* d_out, int out_size) {
    const float* z    = (const float*)d_in[0];
    const float* emb  = (const float*)d_in[1];
    const float* W    = (const float*)d_in[2];
    const float* bias = (const float*)d_in[3];
    float* out = (float*)d_out;

    (void)in_sizes; (void)n_in; (void)out_size;

    compute_P_kernel<<<1024, 256>>>(emb, W, out);

    cudaFuncSetAttribute(vq_kernel, cudaFuncAttributeMaxDynamicSharedMemorySize, (int)VQ_SMEM);
    vq_kernel<<<dim3(8, 16), 256, VQ_SMEM>>>(z, emb, out);

    gather_out_kernel<<<BQ, 256>>>(z, bias, out);
}

// round 4
// speedup vs baseline: 1.6108x; 1.2000x over previous
#include <cuda_runtime.h>

// Problem constants
#define BQ    8192
#define NSUB  16
#define KC    1024
#define EDIM  16
#define DEPTHQ 3
#define DIMQ  256

// Output layout: [loss(1), z_q_out(B*256), onehot(B*16*1024), idx(B*16)]
#define OFF_LOSS   ((size_t)0)
#define OFF_ZQ     ((size_t)1)
#define OFF_ONEHOT ((size_t)(1 + BQ * DIMQ))
#define OFF_IDX    ((size_t)(OFF_ONEHOT + (size_t)BQ * NSUB * KC))

__device__ float g_P[(size_t)NSUB * KC * DIMQ];
__device__ int   g_idx[(size_t)BQ * NSUB * DEPTHQ];

// ---------------- packed f32x2 helpers ----------------
__device__ __forceinline__ unsigned long long pack2(float a, float b) {
    unsigned long long r;
    asm("mov.b64 %0, {%1,%2};" : "=l"(r) : "f"(a), "f"(b));
    return r;
}
__device__ __forceinline__ void fma2(unsigned long long& d, unsigned long long a, unsigned long long b) {
    asm("fma.rn.f32x2 %0, %1, %2, %0;" : "+l"(d) : "l"(a), "l"(b));
}
__device__ __forceinline__ unsigned long long fma2v(unsigned long long a, unsigned long long b, unsigned long long c) {
    unsigned long long r;
    asm("fma.rn.f32x2 %0, %1, %2, %3;" : "=l"(r) : "l"(a), "l"(b), "l"(c));
    return r;
}
__device__ __forceinline__ unsigned long long add2(unsigned long long a, unsigned long long b) {
    unsigned long long r;
    asm("add.rn.f32x2 %0, %1, %2;" : "=l"(r) : "l"(a), "l"(b));
    return r;
}
__device__ __forceinline__ void unpack2(unsigned long long v, float& lo, float& hi) {
    asm("mov.b64 {%0,%1}, %2;" : "=f"(lo), "=f"(hi) : "l"(v));
}

// ---------------- kernel 1: P precompute (+ zero loss slot) ----------------
__global__ void compute_P_kernel(const float* __restrict__ emb,
                                 const float* __restrict__ W,
                                 float* __restrict__ out) {
    if (blockIdx.x == 0 && threadIdx.x == 0) out[OFF_LOSS] = 0.0f;

    const int n  = blockIdx.x >> 6;
    const int k0 = (blockIdx.x & 63) * 16;
    const int j  = threadIdx.x;

    __shared__ float se[16 * EDIM];
    se[j] = emb[((size_t)n * KC + k0) * EDIM + j];

    float w[16];
#pragma unroll
    for (int i = 0; i < 16; i++) w[i] = W[(size_t)(n * 16 + i) * DIMQ + j];
    __syncthreads();

#pragma unroll
    for (int kk = 0; kk < 16; kk++) {
        float acc = 0.0f;
#pragma unroll
        for (int i = 0; i < 16; i++) acc = fmaf(se[kk * EDIM + i], w[i], acc);
        g_P[((size_t)n * KC + (k0 + kk)) * DIMQ + j] = acc;
    }
}

// ---------------- kernel 2: VQ search — codes-in-lanes packing ----------------
// grid (16 row-tiles of 512 rows, 16 n), 256 threads, 2 rows/thread.
// SMEM: pc[512][16] u64 where pc[kp][i] = (e[2kp][i], e[2kp+1][i])  -> 64KB
//       espair[512] u64 = (esq[2kp], esq[2kp+1])                     -> 4KB
//       s_last[512] int                                              -> 2KB
#define NKP (KC / 2)
#define VQ_SMEM ((size_t)(NKP * EDIM * 8 + NKP * 8 + 512 * 4))

__global__ void __launch_bounds__(256, 2)
vq_kernel(const float* __restrict__ z,
          const float* __restrict__ emb,
          float* __restrict__ out) {
    extern __shared__ unsigned long long sm[];
    unsigned long long* pc = sm;                                 // pc[kp*16 + i]
    unsigned long long* s_esq = sm + (size_t)NKP * EDIM;         // espair[kp]
    int* s_last = (int*)(s_esq + NKP);                           // 512 ints

    const float* pcf = (const float*)pc;  // e[k][i] at pcf[((k>>1)*16 + i)*2 + (k&1)]

    const int n = blockIdx.y;
    const int rowbase = blockIdx.x * 512;
    const int tid = threadIdx.x;

    // Build paired codebook + esq (sequential fmaf chain per code — matches ref)
    for (int kp = tid; kp < NKP; kp += 256) {
        const float* e0 = emb + ((size_t)n * KC + 2 * kp) * EDIM;
        const float* e1 = e0 + EDIM;
        float esq0 = 0.0f, esq1 = 0.0f;
        unsigned long long* m = pc + (size_t)kp * EDIM;
#pragma unroll
        for (int i = 0; i < 16; i++) {
            float v0 = __ldg(e0 + i);
            float v1 = __ldg(e1 + i);
            esq0 = fmaf(v0, v0, esq0);
            esq1 = fmaf(v1, v1, esq1);
            m[i] = pack2(v0, v1);
        }
        s_esq[kp] = pack2(esq0, esq1);
    }
    __syncthreads();

    // Two rows per thread: A = rowbase+tid, B = rowbase+256+tid.
    // z duplicated into both lanes (codes vary per lane).
    const int bA = rowbase + tid;
    const int bB = rowbase + 256 + tid;
    unsigned long long zdA[16], zdB[16];
    unsigned long long zsqA2, zsqB2;
    {
        const float* zA = z + (size_t)bA * DIMQ + n * EDIM;
        const float* zB = z + (size_t)bB * DIMQ + n * EDIM;
        float sA = 0.0f, sB = 0.0f;
#pragma unroll
        for (int i = 0; i < 16; i++) {
            float a = zA[i], b = zB[i];
            zdA[i] = pack2(a, a);
            zdB[i] = pack2(b, b);
            sA = fmaf(a, a, sA);
            sB = fmaf(b, b, sB);
        }
        zsqA2 = pack2(sA, sA);
        zsqB2 = pack2(sB, sB);
    }

    const unsigned long long NEG2 = 0xC0000000C0000000ull;  // (-2.f, -2.f)

    for (int d = 0; d < DEPTHQ; d++) {
        float bsA = 3.4e38f, bdA = 3.4e38f;
        float bsB = 3.4e38f, bdB = 3.4e38f;
        int bkA = 0, bkB = 0;

#pragma unroll 1
        for (int kp = 0; kp < NKP; ++kp) {
            const ulonglong2* mv = (const ulonglong2*)(pc + (size_t)kp * EDIM);
            ulonglong2 m0 = mv[0], m1 = mv[1], m2 = mv[2], m3 = mv[3];
            ulonglong2 m4 = mv[4], m5 = mv[5], m6 = mv[6], m7 = mv[7];

            unsigned long long aA = 0ull, aB = 0ull;
            // sequential i = 0..15 per lane (bit-matches scalar fmaf chain)
            fma2(aA, zdA[0],  m0.x); fma2(aB, zdB[0],  m0.x);
            fma2(aA, zdA[1],  m0.y); fma2(aB, zdB[1],  m0.y);
            fma2(aA, zdA[2],  m1.x); fma2(aB, zdB[2],  m1.x);
            fma2(aA, zdA[3],  m1.y); fma2(aB, zdB[3],  m1.y);
            fma2(aA, zdA[4],  m2.x); fma2(aB, zdB[4],  m2.x);
            fma2(aA, zdA[5],  m2.y); fma2(aB, zdB[5],  m2.y);
            fma2(aA, zdA[6],  m3.x); fma2(aB, zdB[6],  m3.x);
            fma2(aA, zdA[7],  m3.y); fma2(aB, zdB[7],  m3.y);
            fma2(aA, zdA[8],  m4.x); fma2(aB, zdB[8],  m4.x);
            fma2(aA, zdA[9],  m4.y); fma2(aB, zdB[9],  m4.y);
            fma2(aA, zdA[10], m5.x); fma2(aB, zdB[10], m5.x);
            fma2(aA, zdA[11], m5.y); fma2(aB, zdB[11], m5.y);
            fma2(aA, zdA[12], m6.x); fma2(aB, zdB[12], m6.x);
            fma2(aA, zdA[13], m6.y); fma2(aB, zdB[13], m6.y);
            fma2(aA, zdA[14], m7.x); fma2(aB, zdB[14], m7.x);
            fma2(aA, zdA[15], m7.y); fma2(aB, zdB[15], m7.y);

            const unsigned long long es2 = s_esq[kp];
            // per lane: s = fmaf(-2, c, zsq) + es  (bit-equal to zsq - 2c, then +es)
            unsigned long long sA2 = add2(fma2v(aA, NEG2, zsqA2), es2);
            unsigned long long sB2 = add2(fma2v(aB, NEG2, zsqB2), es2);

            float slA, shA, slB, shB;
            unpack2(sA2, slA, shA);
            unpack2(sB2, slB, shB);

            // sequential k order: lo lane (k=2kp) strictly before hi lane (2kp+1)
            const bool clA = slA < bsA; bsA = fminf(bsA, slA);
            const bool chA = shA < bsA; bsA = fminf(bsA, shA);
            const bool clB = slB < bsB; bsB = fminf(bsB, slB);
            const bool chB = shB < bsB; bsB = fminf(bsB, shB);

            // rare path: reference compares d = sqrt(max(s,0)); sqrt can collapse
            // adjacent s -> equal d -> argmin keeps the LOWER index.
            if (clA | chA | clB | chB) {
                if (clA) { float dv = sqrtf(fmaxf(slA, 0.0f)); if (dv < bdA) { bdA = dv; bkA = 2 * kp; } }
                if (chA) { float dv = sqrtf(fmaxf(shA, 0.0f)); if (dv < bdA) { bdA = dv; bkA = 2 * kp + 1; } }
                if (clB) { float dv = sqrtf(fmaxf(slB, 0.0f)); if (dv < bdB) { bdB = dv; bkB = 2 * kp; } }
                if (chB) { float dv = sqrtf(fmaxf(shB, 0.0f)); if (dv < bdB) { bdB = dv; bkB = 2 * kp + 1; } }
            }
        }

        // Residual update (one fp32 sub per component, matching ref), zsq refresh
        {
            const size_t baseA = ((size_t)(bkA >> 1) * EDIM) * 2 + (bkA & 1);
            const size_t baseB = ((size_t)(bkB >> 1) * EDIM) * 2 + (bkB & 1);
            float sA = 0.0f, sB = 0.0f;
#pragma unroll
            for (int i = 0; i < 16; i++) {
                float a, dummy, b;
                unpack2(zdA[i], a, dummy);
                unpack2(zdB[i], b, dummy);
                a = a - pcf[baseA + 2 * i];
                b = b - pcf[baseB + 2 * i];
                sA = fmaf(a, a, sA);
                sB = fmaf(b, b, sB);
                zdA[i] = pack2(a, a);
                zdB[i] = pack2(b, b);
            }
            zsqA2 = pack2(sA, sA);
            zsqB2 = pack2(sB, sB);
        }

        g_idx[((size_t)bA * NSUB + n) * DEPTHQ + d] = bkA;
        g_idx[((size_t)bB * NSUB + n) * DEPTHQ + d] = bkB;
        if (d == DEPTHQ - 1) {
            s_last[tid] = bkA;
            s_last[256 + tid] = bkB;
            out[OFF_IDX + (size_t)bA * NSUB + n] = (float)bkA;
            out[OFF_IDX + (size_t)bB * NSUB + n] = (float)bkB;
        }
    }
    __syncthreads();

    // Onehot rows (last depth): coalesced per-row warp writes
    const int w = tid >> 5, lane = tid & 31;
    for (int rl = w * 64; rl < (w + 1) * 64; rl++) {
        const int b = rowbase + rl;
        const int k1 = s_last[rl];
        float* dst = out + OFF_ONEHOT + ((size_t)b * NSUB + n) * KC;
        for (int j = lane; j < KC; j += 32) dst[j] = (j == k1) ? 1.0f : 0.0f;
    }
}

// ---------------- kernel 3: z_q gather + z_q_out + loss ----------------
__global__ void gather_out_kernel(const float* __restrict__ z,
                                  const float* __restrict__ bias,
                                  float* __restrict__ out) {
    const int b = blockIdx.x;
    const int j = threadIdx.x;
    __shared__ int sidx[48];
    __shared__ float sred[8];

    if (j < 48) sidx[j] = g_idx[(size_t)b * 48 + j];
    __syncthreads();

    float acc = 0.0f;
#pragma unroll
    for (int n = 0; n < NSUB; n++) {
#pragma unroll
        for (int d = 0; d < DEPTHQ; d++) {
            const int k = sidx[n * 3 + d];
            acc += g_P[(((size_t)n << 10) + k) * DIMQ + j];
        }
    }
    const float zq = acc * (1.0f / 3.0f) + bias[j];
    const float zv = z[(size_t)b * DIMQ + j];
    const float diff = zq - zv;
    out[OFF_ZQ + (size_t)b * DIMQ + j] = zv + diff;

    float p = diff * diff;
#pragma unroll
    for (int off = 16; off > 0; off >>= 1) p += __shfl_down_sync(0xffffffffu, p, off);
    if ((j & 31) == 0) sred[j >> 5] = p;
    __syncthreads();
    if (j == 0) {
        float s = 0.0f;
#pragma unroll
        for (int i = 0; i < 8; i++) s += sred[i];
        atomicAdd(out + OFF_LOSS, s * (1.25f / (float)(BQ * DIMQ)));
    }
}

// ---------------- launcher ----------------
extern "C" void kernel_launch(void* const* d_in, const int* in_sizes, int n_in,
                              void* d_out, int out_size) {
    const float* z    = (const float*)d_in[0];
    const float* emb  = (const float*)d_in[1];
    const float* W    = (const float*)d_in[2];
    const float* bias = (const float*)d_in[3];
    float* out = (float*)d_out;

    (void)in_sizes; (void)n_in; (void)out_size;

    compute_P_kernel<<<1024, 256>>>(emb, W, out);

    cudaFuncSetAttribute(vq_kernel, cudaFuncAttributeMaxDynamicSharedMemorySize, (int)VQ_SMEM);
    vq_kernel<<<dim3(16, 16), 256, VQ_SMEM>>>(z, emb, out);

    gather_out_kernel<<<BQ, 256>>>(z, bias, out);
}